// round 6
// baseline (speedup 1.0000x reference)
#include <cuda_runtime.h>

#define FULLMASK 0xffffffffu

__device__ __forceinline__ float shx(float v, int m) {
    return __shfl_xor_sync(FULLMASK, v, m);
}

// ---------------------------------------------------------------------------
// Twisted-frame 9-qubit simulation in the CNOT-conjugated frame.
//   amp index i = lane*16 + r  (lane = bits 8..4, r = bits 3..0)
//   u[r] = Re amp(i),  w[r] = Im amp(i ^ T)   (T = current twist)
// Generalized RX with mask m, when T == m, is a LOCAL Givens per index:
//   u' = c*u + s*w ;  w' = c*w - s*u
// Re-twist by d = m_next ^ T: w_new[r] = shfl_xor(w[r ^ dreg], dlane)
// (reg part free, lane part = 16 shfls for the single Im component).
// ---------------------------------------------------------------------------

__device__ __forceinline__ void rot(float (&u)[16], float (&w)[16],
                                    float c, float s) {
#pragma unroll
    for (int r = 0; r < 16; ++r) {
        float uu = u[r];
        u[r] = fmaf(c, uu, s * w[r]);
        w[r] = fmaf(c, w[r], -s * uu);
    }
}

template<int DL, int DR>
__device__ __forceinline__ void retwist(float (&w)[16]) {
    float t[16];
#pragma unroll
    for (int r = 0; r < 16; ++r)
        t[r] = (DL != 0) ? shx(w[r ^ DR], DL) : w[r ^ DR];
#pragma unroll
    for (int r = 0; r < 16; ++r) w[r] = t[r];
}

__global__ void __launch_bounds__(128)
quanv_kernel(const float* __restrict__ x,   // (4,3,28,28)
             const float* __restrict__ w,   // (2,9)
             float* __restrict__ out)       // (4,4,26,26)
{
    __shared__ float cw1[9], sw1[9], w0s[9];
    if (threadIdx.x < 9) {
        __sincosf(0.5f * w[9 + threadIdx.x], &sw1[threadIdx.x], &cw1[threadIdx.x]);
        w0s[threadIdx.x] = w[threadIdx.x];
    }
    __syncthreads();

    const int lane = threadIdx.x & 31;
    const int g = blockIdx.x * 4 + (threadIdx.x >> 5);   // [0,2704)
    const int b = g / 676;
    int rem = g - b * 676;
    const int oy = rem / 26;
    const int ox = rem - oy * 26;

    // hoist layer-2 trig + layer-1 weights into registers
    float c2[9], s2[9], w0r[9];
#pragma unroll
    for (int q = 0; q < 9; ++q) { c2[q] = cw1[q]; s2[q] = sw1[q]; w0r[q] = w0s[q]; }

    // measurement lane signs: parity(lane & laneMask(row_f(M^2)))
    const float sg0 = (__popc(lane & 0x05) & 1) ? -1.f : 1.f;  // row 0x055
    const float sg1 = (__popc(lane & 0x17) & 1) ? -1.f : 1.f;  // row 0x17F
    const float sg2 = (__popc(lane & 0x0B) & 1) ? -1.f : 1.f;  // row 0x0BF
    const float sg3 = (__popc(lane & 0x15) & 1) ? -1.f : 1.f;  // row 0x15F

    // (-i)^popc phases at lane and lane^0x18 (for the initial twist T=0x180)
    const int lk  = __popc(lane) & 3;
    const int lk2 = __popc(lane ^ 0x18) & 3;
    const float wx  = (lk  == 0) ? 1.f : (lk  == 2) ? -1.f : 0.f;
    const float wy  = (lk  == 3) ? 1.f : (lk  == 1) ? -1.f : 0.f;
    const float wx2 = (lk2 == 0) ? 1.f : (lk2 == 2) ? -1.f : 0.f;
    const float wy2 = (lk2 == 3) ? 1.f : (lk2 == 1) ? -1.f : 0.f;

    float sAsum = 0.f, sBsum = 0.f;

    for (int ch = 0; ch < 3; ++ch) {
        // fused angles theta_q = patch[q] + w0[q]
        const float* xp = x + ((b * 3 + ch) * 28 + oy) * 28 + ox;
        float cq[9], sq[9];
#pragma unroll
        for (int q = 0; q < 9; ++q) {
            float v = xp[(q / 3) * 28 + (q % 3)] + w0r[q];
            __sincosf(0.5f * v, &sq[q], &cq[q]);
        }

        // product-state magnitudes
        // lane bits 16,8,4,2,1 -> qubits 0..4 ; r bits 8,4,2,1 -> qubits 5..8
        const float base = ((lane & 4) ? sq[2] : cq[2])
                         * ((lane & 2) ? sq[3] : cq[3])
                         * ((lane & 1) ? sq[4] : cq[4]);
        const float LM0 = base * ((lane & 16) ? sq[0] : cq[0])
                               * ((lane &  8) ? sq[1] : cq[1]);
        const float LM1 = base * ((lane & 16) ? cq[0] : sq[0])   // lane^0x18
                               * ((lane &  8) ? cq[1] : sq[1]);
        float hi[4], lo[4];
        hi[0] = cq[5] * cq[6];  hi[1] = cq[5] * sq[6];
        hi[2] = sq[5] * cq[6];  hi[3] = sq[5] * sq[6];
        lo[0] = cq[7] * cq[8];  lo[1] = cq[7] * sq[8];
        lo[2] = sq[7] * cq[8];  lo[3] = sq[7] * sq[8];

        // init with twist T = 0x180:
        //   u[r] = mag(i)        * Re((-i)^popc(i))
        //   w[r] = mag(i^0x180)  * Im((-i)^popc(i^0x180))   (reg part of mag shared)
        float u[16], wv[16];
#pragma unroll
        for (int r = 0; r < 16; ++r) {
            const float m  = hi[r >> 2] * lo[r & 3];
            const int pr = __popc(r) & 3;              // compile-time after unroll
            // Re((-i)^pr * (wx + i wy)) ; Im((-i)^pr * (wx2 + i wy2))
            const float ux = (pr == 0) ?  wx  : (pr == 1) ?  wy  : (pr == 2) ? -wx  : -wy;
            const float vy = (pr == 0) ?  wy2 : (pr == 1) ? -wx2 : (pr == 2) ? -wy2 :  wx2;
            u[r]  = (m * LM0) * ux;
            wv[r] = (m * LM1) * vy;
        }

        // layer-2 rotations, twisted frame. masks: 0x180,0xC0,0x60,0x30,
        // 0x18,0xC,0x6,0x3,0x181 ; deltas between = retwist args below.
        rot(u, wv, c2[0], s2[0]);                 // T=0x180, q0 local
        retwist<0x14, 0>(wv);   rot(u, wv, c2[1], s2[1]);  // T=0x0C0
        retwist<0x0A, 0>(wv);   rot(u, wv, c2[2], s2[2]);  // T=0x060
        retwist<0x05, 0>(wv);   rot(u, wv, c2[3], s2[3]);  // T=0x030
        retwist<0x02, 8>(wv);   rot(u, wv, c2[4], s2[4]);  // T=0x018
        retwist<0x01, 4>(wv);   rot(u, wv, c2[5], s2[5]);  // T=0x00C
        retwist<0x00, 0xA>(wv); rot(u, wv, c2[6], s2[6]);  // T=0x006
        retwist<0x00, 0x5>(wv); rot(u, wv, c2[7], s2[7]);  // T=0x003
        retwist<0x18, 2>(wv);   rot(u, wv, c2[8], s2[8]);  // T=0x181

        // measurement. Final twist T=0x181:
        //   parity(T & S_0)=1 -> w-part sign flips for sA ; even for S_1..S_3.
        float sA = 0.f, sB = 0.f;
#pragma unroll
        for (int r = 0; r < 16; ++r) {
            const float pu = u[r] * u[r];
            const float pw = wv[r] * wv[r];
            const float fA = (__popc(r & 5) & 1) ? -1.f : 1.f;
            const float fB = (__popc(r)     & 1) ? -1.f : 1.f;
            sA += fA * (pu - pw);
            sB += fB * (pu + pw);
        }
        sAsum += sA;
        sBsum += sB;
    }

    float z0 = sg0 * sAsum;
    float z1 = sg1 * sBsum;
    float z2 = sg2 * sBsum;
    float z3 = sg3 * sBsum;
#pragma unroll
    for (int off = 16; off >= 1; off >>= 1) {
        z0 += shx(z0, off);
        z1 += shx(z1, off);
        z2 += shx(z2, off);
        z3 += shx(z3, off);
    }

    if (lane == 0) {
        const float inv3 = 1.0f / 3.0f;
        out[((b * 4 + 0) * 26 + oy) * 26 + ox] = z0 * inv3;
        out[((b * 4 + 1) * 26 + oy) * 26 + ox] = z1 * inv3;
        out[((b * 4 + 2) * 26 + oy) * 26 + ox] = z2 * inv3;
        out[((b * 4 + 3) * 26 + oy) * 26 + ox] = z3 * inv3;
    }
}

extern "C" void kernel_launch(void* const* d_in, const int* in_sizes, int n_in,
                              void* d_out, int out_size) {
    const float* x = (const float*)d_in[0];   // (4,3,28,28) f32
    const float* w = (const float*)d_in[1];   // (2,9) f32
    float* out = (float*)d_out;               // (4,4,26,26) f32
    quanv_kernel<<<676, 128>>>(x, w, out);
}